// round 10
// baseline (speedup 1.0000x reference)
#include <cuda_runtime.h>
#include <cuda_bf16.h>
#include <mma.h>
#include <cstdint>

using namespace nvcuda;

#define NN 100000
#define NE 600000

// ---------------- scratch (device globals; no allocation allowed) ----------------
__device__ float g_a  [(size_t)NN * 128];
__device__ float g_b  [(size_t)NN * 128];
__device__ float g_p  [(size_t)NN * 128];
__device__ float g_q  [(size_t)NN * 128];   // second projection buffer (breaks gather/write alias)
__device__ __nv_bfloat16 g_wb[229376];
// CSR build
__device__ int g_cnt   [NN];
__device__ int g_rowtmp[NN];
__device__ int g_rowptr[NN + 1];
__device__ int g_cur   [NN];
__device__ int g_bsum  [256];
__device__ int g_eid   [NE];

// smem layout (bytes): Ahi@0, Alo@17408, Whi@34816, Wlo@69632 -> total 104448
#define PP    136
#define ASZ   17408
#define WOFF  34816
#define SMEMB 104448
#define CP    132

__device__ __forceinline__ void split2(float a, float b, uint32_t& hi, uint32_t& lo) {
    __nv_bfloat16 ha = __float2bfloat16(a), hb = __float2bfloat16(b);
    float ra = a - __bfloat162float(ha), rb = b - __bfloat162float(hb);
    __nv_bfloat16 la = __float2bfloat16(ra), lb = __float2bfloat16(rb);
    hi = ((uint32_t)__bfloat16_as_ushort(hb) << 16) | (uint32_t)__bfloat16_as_ushort(ha);
    lo = ((uint32_t)__bfloat16_as_ushort(lb) << 16) | (uint32_t)__bfloat16_as_ushort(la);
}

// ---------------- weight conversion ----------------
struct WSrc { const float* s[8]; };

__global__ void wconv_k(WSrc ws) {
    int idx = blockIdx.x * blockDim.x + threadIdx.x;
    if (idx >= 114688) return;
    int m, r, ncols;
    if (idx < 98304) { m = idx >> 14; r = idx & 16383; ncols = 128; }
    else             { m = 6 + ((idx - 98304) >> 13); r = (idx - 98304) & 8191; ncols = 64; }
    int k = r / ncols, n = r % ncols;
    float v = ws.s[m][r];
    __nv_bfloat16 h = __float2bfloat16(v);
    __nv_bfloat16 l = __float2bfloat16(v - __bfloat162float(h));
    int base, nc;
    if (m < 6)      { const int offs[6] = {0, 32768, 65536, 98304, 131072, 163840};
                      base = offs[m]; nc = n; }
    else if (m == 6){ base = 196608; nc = n; }
    else            { base = 196608; nc = 64 + n; }
    g_wb[base + nc * 128 + k]         = h;
    g_wb[base + 16384 + nc * 128 + k] = l;
}

// ================= CSR build =================
__global__ void czero_k() {
    int i = blockIdx.x * blockDim.x + threadIdx.x;
    if (i < NN) g_cnt[i] = 0;
}
__global__ void hist_k(const int* __restrict__ dst) {
    int e = blockIdx.x * blockDim.x + threadIdx.x;
    if (e < NE) atomicAdd(&g_cnt[dst[e]], 1);
}
__global__ void scan1_k() {
    __shared__ int sm[512];
    int i = blockIdx.x * 512 + threadIdx.x;
    int v = (i < NN) ? g_cnt[i] : 0;
    sm[threadIdx.x] = v;
    __syncthreads();
#pragma unroll
    for (int off = 1; off < 512; off <<= 1) {
        int t = (threadIdx.x >= off) ? sm[threadIdx.x - off] : 0;
        __syncthreads();
        sm[threadIdx.x] += t;
        __syncthreads();
    }
    if (i < NN) g_rowtmp[i] = sm[threadIdx.x];
    if (threadIdx.x == 511) g_bsum[blockIdx.x] = sm[511];
}
__global__ void scan2_k() {
    __shared__ int sm[256];
    int v = (threadIdx.x < 196) ? g_bsum[threadIdx.x] : 0;
    sm[threadIdx.x] = v;
    __syncthreads();
#pragma unroll
    for (int off = 1; off < 256; off <<= 1) {
        int t = (threadIdx.x >= off) ? sm[threadIdx.x - off] : 0;
        __syncthreads();
        sm[threadIdx.x] += t;
        __syncthreads();
    }
    if (threadIdx.x < 196) g_bsum[threadIdx.x] = (threadIdx.x == 0) ? 0 : sm[threadIdx.x - 1];
}
__global__ void scan3_k() {
    int i = blockIdx.x * 512 + threadIdx.x;
    if (i < NN) {
        int rp = g_rowtmp[i] - g_cnt[i] + g_bsum[blockIdx.x];
        g_rowptr[i] = rp;
        g_cur[i]    = rp;
    }
    if (i == 0) g_rowptr[NN] = NE;
}
__global__ void fill_k(const int* __restrict__ src, const int* __restrict__ dst) {
    int e = blockIdx.x * blockDim.x + threadIdx.x;
    if (e >= NE) return;
    int pos = atomicAdd(&g_cur[dst[e]], 1);
    g_eid[pos] = src[e];
}

// ================= standalone gather (final layer only) =================
__global__ __launch_bounds__(256)
void gath64_k(const float* __restrict__ p, float* __restrict__ out) {
    int w    = (blockIdx.x * 256 + threadIdx.x) >> 5;
    int lane = threadIdx.x & 31;
    if (w >= NN) return;
    int beg = g_rowptr[w], end = g_rowptr[w + 1];
    float2 acc = make_float2(0.f, 0.f);
    int e = beg;
    for (; e + 1 < end; e += 2) {
        int s0 = g_eid[e], s1 = g_eid[e + 1];
        float2 v0 = *reinterpret_cast<const float2*>(p + (size_t)s0 * 64 + lane * 2);
        float2 v1 = *reinterpret_cast<const float2*>(p + (size_t)s1 * 64 + lane * 2);
        acc.x += v0.x + v1.x; acc.y += v0.y + v1.y;
    }
    if (e < end) {
        int s0 = g_eid[e];
        float2 v0 = *reinterpret_cast<const float2*>(p + (size_t)s0 * 64 + lane * 2);
        acc.x += v0.x; acc.y += v0.y;
    }
    float inv = 1.0f / fmaxf((float)(end - beg), 1.0f);
    float2 o = *reinterpret_cast<const float2*>(out + (size_t)w * 64 + lane * 2);
    o.x += acc.x * inv; o.y += acc.y * inv;
    *reinterpret_cast<float2*>(out + (size_t)w * 64 + lane * 2) = o;
}

// ================= GEMM building blocks =================
template<bool RELU>
__device__ __forceinline__ void loadA(char* dsm, const float* __restrict__ A, int m0, int M, int tid) {
    __nv_bfloat16* Ahi = reinterpret_cast<__nv_bfloat16*>(dsm);
    __nv_bfloat16* Alo = reinterpret_cast<__nv_bfloat16*>(dsm + ASZ);
#pragma unroll
    for (int i = 0; i < 8; ++i) {
        int idx = tid + i * 256;
        int m   = idx >> 5;
        int k0  = (idx & 31) * 4;
        float4 v = make_float4(0.f, 0.f, 0.f, 0.f);
        int gm = m0 + m;
        if (gm < M) v = *reinterpret_cast<const float4*>(A + (size_t)gm * 128 + k0);
        if (RELU) { v.x = fmaxf(v.x, 0.f); v.y = fmaxf(v.y, 0.f); v.z = fmaxf(v.z, 0.f); v.w = fmaxf(v.w, 0.f); }
        uint32_t h0, l0, h1, l1;
        split2(v.x, v.y, h0, l0);
        split2(v.z, v.w, h1, l1);
        *reinterpret_cast<uint2*>(&Ahi[m * PP + k0]) = make_uint2(h0, h1);
        *reinterpret_cast<uint2*>(&Alo[m * PP + k0]) = make_uint2(l0, l1);
    }
}

// fused: A row = relu( self[gm] + mean_{s in N(gm)} pnb[s] ), split -> smem
// warp w handles rows w*8 .. w*8+7; lane owns float4 column slice.
__device__ __forceinline__ void loadA_gather(char* dsm, const float* __restrict__ self,
                                             const float* __restrict__ pnb, int m0, int M, int tid) {
    __nv_bfloat16* Ahi = reinterpret_cast<__nv_bfloat16*>(dsm);
    __nv_bfloat16* Alo = reinterpret_cast<__nv_bfloat16*>(dsm + ASZ);
    const int wid = tid >> 5, lane = tid & 31, c = lane * 4;
#pragma unroll 2
    for (int r = 0; r < 8; ++r) {
        int m  = wid * 8 + r;
        int gm = m0 + m;
        float4 acc = make_float4(0.f, 0.f, 0.f, 0.f);
        float4 v   = make_float4(0.f, 0.f, 0.f, 0.f);
        float inv  = 1.0f;
        if (gm < M) {
            int beg = g_rowptr[gm], end = g_rowptr[gm + 1];
            int e = beg;
            for (; e + 1 < end; e += 2) {
                int s0 = g_eid[e], s1 = g_eid[e + 1];
                float4 v0 = *reinterpret_cast<const float4*>(pnb + (size_t)s0 * 128 + c);
                float4 v1 = *reinterpret_cast<const float4*>(pnb + (size_t)s1 * 128 + c);
                acc.x += v0.x + v1.x; acc.y += v0.y + v1.y;
                acc.z += v0.z + v1.z; acc.w += v0.w + v1.w;
            }
            if (e < end) {
                int s0 = g_eid[e];
                float4 v0 = *reinterpret_cast<const float4*>(pnb + (size_t)s0 * 128 + c);
                acc.x += v0.x; acc.y += v0.y; acc.z += v0.z; acc.w += v0.w;
            }
            inv = 1.0f / fmaxf((float)(end - beg), 1.0f);
            v = *reinterpret_cast<const float4*>(self + (size_t)gm * 128 + c);
        }
        v.x = fmaxf(v.x + acc.x * inv, 0.f);
        v.y = fmaxf(v.y + acc.y * inv, 0.f);
        v.z = fmaxf(v.z + acc.z * inv, 0.f);
        v.w = fmaxf(v.w + acc.w * inv, 0.f);
        uint32_t h0, l0, h1, l1;
        split2(v.x, v.y, h0, l0);
        split2(v.z, v.w, h1, l1);
        *reinterpret_cast<uint2*>(&Ahi[m * PP + c]) = make_uint2(h0, h1);
        *reinterpret_cast<uint2*>(&Alo[m * PP + c]) = make_uint2(l0, l1);
    }
}

__device__ __forceinline__ void loadW(char* dsm, const __nv_bfloat16* __restrict__ whi,
                                      const __nv_bfloat16* __restrict__ wlo, int tid) {
    __nv_bfloat16* Whi = reinterpret_cast<__nv_bfloat16*>(dsm + WOFF);
    __nv_bfloat16* Wlo = reinterpret_cast<__nv_bfloat16*>(dsm + WOFF + ASZ * 2);
#pragma unroll
    for (int i = 0; i < 16; ++i) {
        int idx  = tid + i * 256;
        int half = idx >> 11;
        int r    = idx & 2047;
        int n    = r >> 4;
        int c    = r & 15;
        const uint4* srcp = reinterpret_cast<const uint4*>(half ? wlo : whi);
        __nv_bfloat16* dp = half ? Wlo : Whi;
        *reinterpret_cast<uint4*>(reinterpret_cast<char*>(&dp[n * PP]) + c * 16) = srcp[n * 16 + c];
    }
}

typedef wmma::fragment<wmma::accumulator, 16, 16, 16, float> AccF;

__device__ __forceinline__ void mmaStage(char* dsm, AccF acc[2][2], int wr, int wc) {
    __nv_bfloat16* Ahi = reinterpret_cast<__nv_bfloat16*>(dsm);
    __nv_bfloat16* Alo = reinterpret_cast<__nv_bfloat16*>(dsm + ASZ);
    __nv_bfloat16* Whi = reinterpret_cast<__nv_bfloat16*>(dsm + WOFF);
    __nv_bfloat16* Wlo = reinterpret_cast<__nv_bfloat16*>(dsm + WOFF + ASZ * 2);
#pragma unroll
    for (int i = 0; i < 2; ++i)
#pragma unroll
        for (int j = 0; j < 2; ++j) wmma::fill_fragment(acc[i][j], 0.0f);
#pragma unroll
    for (int ks = 0; ks < 8; ++ks) {
        const int k = ks * 16;
        wmma::fragment<wmma::matrix_a, 16, 16, 16, __nv_bfloat16, wmma::row_major> ah[2], al[2];
        wmma::fragment<wmma::matrix_b, 16, 16, 16, __nv_bfloat16, wmma::col_major> bh[2], bl[2];
#pragma unroll
        for (int i = 0; i < 2; ++i) {
            int m = wr * 32 + i * 16;
            wmma::load_matrix_sync(ah[i], &Ahi[m * PP + k], PP);
            wmma::load_matrix_sync(al[i], &Alo[m * PP + k], PP);
        }
#pragma unroll
        for (int j = 0; j < 2; ++j) {
            int n = wc * 32 + j * 16;
            wmma::load_matrix_sync(bh[j], &Whi[n * PP + k], PP);
            wmma::load_matrix_sync(bl[j], &Wlo[n * PP + k], PP);
        }
#pragma unroll
        for (int i = 0; i < 2; ++i)
#pragma unroll
            for (int j = 0; j < 2; ++j) {
                wmma::mma_sync(acc[i][j], ah[i], bh[j], acc[i][j]);
                wmma::mma_sync(acc[i][j], ah[i], bl[j], acc[i][j]);
                wmma::mma_sync(acc[i][j], al[i], bh[j], acc[i][j]);
            }
    }
}

__device__ __forceinline__ void accToStaging(char* dsm, AccF acc[2][2], int wr, int wc) {
    float* Cs = reinterpret_cast<float*>(dsm + WOFF);
#pragma unroll
    for (int i = 0; i < 2; ++i)
#pragma unroll
        for (int j = 0; j < 2; ++j)
            wmma::store_matrix_sync(&Cs[(wr * 32 + i * 16) * CP + wc * 32 + j * 16], acc[i][j], CP, wmma::mem_row_major);
}

__device__ __forceinline__ void stagingToA(char* dsm, const float* __restrict__ bias, int tid) {
    const float* Cs = reinterpret_cast<const float*>(dsm + WOFF);
    __nv_bfloat16* Ahi = reinterpret_cast<__nv_bfloat16*>(dsm);
    __nv_bfloat16* Alo = reinterpret_cast<__nv_bfloat16*>(dsm + ASZ);
#pragma unroll
    for (int i = 0; i < 8; ++i) {
        int idx = tid + i * 256;
        int m   = idx >> 5;
        int c   = (idx & 31) * 4;
        float4 v = *reinterpret_cast<const float4*>(&Cs[m * CP + c]);
        v.x = fmaxf(v.x + bias[c + 0], 0.f);
        v.y = fmaxf(v.y + bias[c + 1], 0.f);
        v.z = fmaxf(v.z + bias[c + 2], 0.f);
        v.w = fmaxf(v.w + bias[c + 3], 0.f);
        uint32_t h0, l0, h1, l1;
        split2(v.x, v.y, h0, l0);
        split2(v.z, v.w, h1, l1);
        *reinterpret_cast<uint2*>(&Ahi[m * PP + c]) = make_uint2(h0, h1);
        *reinterpret_cast<uint2*>(&Alo[m * PP + c]) = make_uint2(l0, l1);
    }
}

template<bool BIAS>
__device__ __forceinline__ void stagingToGlobal(char* dsm, const float* __restrict__ bias,
                                                float* __restrict__ C, int m0, int M, int tid) {
    const float* Cs = reinterpret_cast<const float*>(dsm + WOFF);
#pragma unroll
    for (int i = 0; i < 8; ++i) {
        int idx = tid + i * 256;
        int m   = idx >> 5;
        int c   = (idx & 31) * 4;
        int gm  = m0 + m;
        if (gm >= M) continue;
        float4 o = *reinterpret_cast<const float4*>(&Cs[m * CP + c]);
        if (BIAS) { o.x += bias[c]; o.y += bias[c + 1]; o.z += bias[c + 2]; o.w += bias[c + 3]; }
        *reinterpret_cast<float4*>(C + (size_t)gm * 128 + c) = o;
    }
}

// ================= fused kernels =================

// K1: x -> { self0(+b) -> p_a ; neigh0 -> p_p }
__global__ __launch_bounds__(256, 2)
void k1_k(const float* __restrict__ x,
          const __nv_bfloat16* __restrict__ s0h, const __nv_bfloat16* __restrict__ s0l,
          const __nv_bfloat16* __restrict__ n0h, const __nv_bfloat16* __restrict__ n0l,
          const float* __restrict__ b0, float* __restrict__ Ca, float* __restrict__ Cp, int M)
{
    extern __shared__ char dsm[];
    const int tid = threadIdx.x, wid = tid >> 5, wr = wid & 1, wc = wid >> 1;
    const int m0 = blockIdx.x * 64;
    AccF acc[2][2];

    loadA<false>(dsm, x, m0, M, tid);
    loadW(dsm, s0h, s0l, tid);
    __syncthreads();
    mmaStage(dsm, acc, wr, wc);
    __syncthreads();
    accToStaging(dsm, acc, wr, wc);
    __syncthreads();
    stagingToGlobal<true>(dsm, b0, Ca, m0, M, tid);
    __syncthreads();
    loadW(dsm, n0h, n0l, tid);
    __syncthreads();
    mmaStage(dsm, acc, wr, wc);
    __syncthreads();
    accToStaging(dsm, acc, wr, wc);
    __syncthreads();
    stagingToGlobal<false>(dsm, nullptr, Cp, m0, M, tid);
}

// K2: A = relu(self0out + gather(pnb)) -> fc(+b,relu) -> fc2(+b,relu) -> { self1(+b)->Cb ; neigh1->Cq }
// NOTE: Cq must NOT alias pnb (cross-CTA WAR hazard through graph edges).
__global__ __launch_bounds__(256, 2)
void k2_k(const float* __restrict__ selfin, const float* __restrict__ pnb,
          const __nv_bfloat16* __restrict__ fch, const __nv_bfloat16* __restrict__ fcl, const float* __restrict__ fcb,
          const __nv_bfloat16* __restrict__ f2h, const __nv_bfloat16* __restrict__ f2l, const float* __restrict__ f2b,
          const __nv_bfloat16* __restrict__ s1h, const __nv_bfloat16* __restrict__ s1l, const float* __restrict__ b1,
          const __nv_bfloat16* __restrict__ n1h, const __nv_bfloat16* __restrict__ n1l,
          float* __restrict__ Cb, float* __restrict__ Cq, int M)
{
    extern __shared__ char dsm[];
    const int tid = threadIdx.x, wid = tid >> 5, wr = wid & 1, wc = wid >> 1;
    const int m0 = blockIdx.x * 64;
    AccF acc[2][2];

    loadA_gather(dsm, selfin, pnb, m0, M, tid);
    loadW(dsm, fch, fcl, tid);
    __syncthreads();
    mmaStage(dsm, acc, wr, wc);
    __syncthreads();
    accToStaging(dsm, acc, wr, wc);
    __syncthreads();
    stagingToA(dsm, fcb, tid);
    __syncthreads();
    loadW(dsm, f2h, f2l, tid);
    __syncthreads();
    mmaStage(dsm, acc, wr, wc);
    __syncthreads();
    accToStaging(dsm, acc, wr, wc);
    __syncthreads();
    stagingToA(dsm, f2b, tid);
    __syncthreads();
    loadW(dsm, s1h, s1l, tid);
    __syncthreads();
    mmaStage(dsm, acc, wr, wc);
    __syncthreads();
    accToStaging(dsm, acc, wr, wc);
    __syncthreads();
    stagingToGlobal<true>(dsm, b1, Cb, m0, M, tid);
    __syncthreads();
    loadW(dsm, n1h, n1l, tid);
    __syncthreads();
    mmaStage(dsm, acc, wr, wc);
    __syncthreads();
    accToStaging(dsm, acc, wr, wc);
    __syncthreads();
    stagingToGlobal<false>(dsm, nullptr, Cq, m0, M, tid);
}

// K3: A = relu(self1out + gather(pnb)) -> packed layer2 W: cols 0-63 -> out (+b2), 64-127 -> Cp
// NOTE: Cp must NOT alias pnb.
__global__ __launch_bounds__(256, 2)
void k3_k(const float* __restrict__ selfin, const float* __restrict__ pnb,
          const __nv_bfloat16* __restrict__ l2h, const __nv_bfloat16* __restrict__ l2l,
          const float* __restrict__ b2, float* __restrict__ Co, float* __restrict__ Cp, int M)
{
    extern __shared__ char dsm[];
    const int tid = threadIdx.x, wid = tid >> 5, wr = wid & 1, wc = wid >> 1;
    const int m0 = blockIdx.x * 64;
    AccF acc[2][2];

    loadA_gather(dsm, selfin, pnb, m0, M, tid);
    loadW(dsm, l2h, l2l, tid);
    __syncthreads();
    mmaStage(dsm, acc, wr, wc);
    __syncthreads();
    accToStaging(dsm, acc, wr, wc);
    __syncthreads();
    const float* Cs = reinterpret_cast<const float*>(dsm + WOFF);
#pragma unroll
    for (int i = 0; i < 8; ++i) {
        int idx = tid + i * 256;
        int m   = idx >> 5;
        int c   = (idx & 31) * 4;
        int gm  = m0 + m;
        if (gm >= M) continue;
        float4 o = *reinterpret_cast<const float4*>(&Cs[m * CP + c]);
        if (c < 64) {
            o.x += b2[c]; o.y += b2[c + 1]; o.z += b2[c + 2]; o.w += b2[c + 3];
            *reinterpret_cast<float4*>(Co + (size_t)gm * 64 + c) = o;
        } else {
            *reinterpret_cast<float4*>(Cp + (size_t)gm * 64 + (c - 64)) = o;
        }
    }
}

// ---------------- launch ----------------
extern "C" void kernel_launch(void* const* d_in, const int* in_sizes, int n_in,
                              void* d_out, int out_size) {
    const float* x        = (const float*)d_in[0];
    const int*   src      = (const int*)  d_in[1];
    const int*   dst      = (const int*)  d_in[2];
    const float* w_self0  = (const float*)d_in[3];
    const float* b_self0  = (const float*)d_in[4];
    const float* w_neigh0 = (const float*)d_in[5];
    const float* fc_w     = (const float*)d_in[6];
    const float* fc_b     = (const float*)d_in[7];
    const float* fc2_w    = (const float*)d_in[8];
    const float* fc2_b    = (const float*)d_in[9];
    const float* w_self1  = (const float*)d_in[10];
    const float* b_self1  = (const float*)d_in[11];
    const float* w_neigh1 = (const float*)d_in[12];
    const float* w_self2  = (const float*)d_in[13];
    const float* b_self2  = (const float*)d_in[14];
    const float* w_neigh2 = (const float*)d_in[15];
    float* out = (float*)d_out;

    float *p_a, *p_b, *p_p, *p_q;
    __nv_bfloat16* p_wb;
    cudaGetSymbolAddress((void**)&p_a,  g_a);
    cudaGetSymbolAddress((void**)&p_b,  g_b);
    cudaGetSymbolAddress((void**)&p_p,  g_p);
    cudaGetSymbolAddress((void**)&p_q,  g_q);
    cudaGetSymbolAddress((void**)&p_wb, g_wb);

    const __nv_bfloat16 *s0h = p_wb,          *s0l = p_wb + 16384;
    const __nv_bfloat16 *n0h = p_wb + 32768,  *n0l = p_wb + 49152;
    const __nv_bfloat16 *fch = p_wb + 65536,  *fcl = p_wb + 81920;
    const __nv_bfloat16 *f2h = p_wb + 98304,  *f2l = p_wb + 114688;
    const __nv_bfloat16 *s1h = p_wb + 131072, *s1l = p_wb + 147456;
    const __nv_bfloat16 *n1h = p_wb + 163840, *n1l = p_wb + 180224;
    const __nv_bfloat16 *l2h = p_wb + 196608, *l2l = p_wb + 212992;

    cudaFuncSetAttribute(k1_k, cudaFuncAttributeMaxDynamicSharedMemorySize, SMEMB);
    cudaFuncSetAttribute(k2_k, cudaFuncAttributeMaxDynamicSharedMemorySize, SMEMB);
    cudaFuncSetAttribute(k3_k, cudaFuncAttributeMaxDynamicSharedMemorySize, SMEMB);

    const int GB = (NN + 63) / 64;   // 1563
    const int T  = 256;
    const int GW = (NN * 32 + T - 1) / T;

    // ---- prep: CSR build + weight preconversion ----
    czero_k<<<(NN + T - 1) / T, T>>>();
    hist_k<<<(NE + T - 1) / T, T>>>(dst);
    scan1_k<<<196, 512>>>();
    scan2_k<<<1, 256>>>();
    scan3_k<<<196, 512>>>();
    fill_k<<<(NE + T - 1) / T, T>>>(src, dst);
    WSrc ws; ws.s[0] = w_self0; ws.s[1] = w_neigh0; ws.s[2] = fc_w; ws.s[3] = fc2_w;
             ws.s[4] = w_self1; ws.s[5] = w_neigh1; ws.s[6] = w_self2; ws.s[7] = w_neigh2;
    wconv_k<<<(114688 + T - 1) / T, T>>>(ws);

    // ---- layer 0 ----
    k1_k<<<GB, T, SMEMB>>>(x, s0h, s0l, n0h, n0l, b_self0, p_a, p_p, NN);

    // ---- fc / fc2 / layer 1 (gather p_p fused; neigh1 -> p_q, no alias) ----
    k2_k<<<GB, T, SMEMB>>>(p_a, p_p, fch, fcl, fc_b, f2h, f2l, fc2_b,
                           s1h, s1l, b_self1, n1h, n1l, p_b, p_q, NN);

    // ---- layer 2 (gather p_q fused; neigh2 -> p_p, no alias) ----
    k3_k<<<GB, T, SMEMB>>>(p_b, p_q, l2h, l2l, b_self2, out, p_p, NN);
    gath64_k<<<GW, T>>>(p_p, out);
}

// round 11
// speedup vs baseline: 1.1142x; 1.1142x over previous
#include <cuda_runtime.h>
#include <cuda_bf16.h>
#include <mma.h>
#include <cstdint>

using namespace nvcuda;

#define NN 100000
#define NE 600000

// ---------------- scratch (device globals; no allocation allowed) ----------------
__device__ float g_a  [(size_t)NN * 128];
__device__ float g_b  [(size_t)NN * 128];
__device__ float g_p  [(size_t)NN * 128];
__device__ __nv_bfloat16 g_wb[229376];   // 7 weight blocks (layer2 pair packed), transposed, hi+lo
// CSR build (atomic allocation; segment order arbitrary — mean is order-independent)
__device__ int g_cnt   [NN];
__device__ int g_rowbeg[NN];
__device__ int g_cur   [NN];
__device__ int g_total;
__device__ int g_eid   [NE];

// smem layout (bytes): Ahi@0, Alo@17408, Whi@34816, Wlo@69632 -> total 104448
#define PP    136
#define ASZ   17408
#define WOFF  34816
#define SMEMB 104448
#define CP    132

__device__ __forceinline__ void split2(float a, float b, uint32_t& hi, uint32_t& lo) {
    __nv_bfloat16 ha = __float2bfloat16(a), hb = __float2bfloat16(b);
    float ra = a - __bfloat162float(ha), rb = b - __bfloat162float(hb);
    __nv_bfloat16 la = __float2bfloat16(ra), lb = __float2bfloat16(rb);
    hi = ((uint32_t)__bfloat16_as_ushort(hb) << 16) | (uint32_t)__bfloat16_as_ushort(ha);
    lo = ((uint32_t)__bfloat16_as_ushort(lb) << 16) | (uint32_t)__bfloat16_as_ushort(la);
}

// ---------------- weight conversion ----------------
struct WSrc { const float* s[8]; };

__global__ void wconv_k(WSrc ws) {
    int idx = blockIdx.x * blockDim.x + threadIdx.x;
    if (idx >= 114688) return;
    int m, r, ncols;
    if (idx < 98304) { m = idx >> 14; r = idx & 16383; ncols = 128; }
    else             { m = 6 + ((idx - 98304) >> 13); r = (idx - 98304) & 8191; ncols = 64; }
    int k = r / ncols, n = r % ncols;
    float v = ws.s[m][r];
    __nv_bfloat16 h = __float2bfloat16(v);
    __nv_bfloat16 l = __float2bfloat16(v - __bfloat162float(h));
    int base, nc;
    if (m < 6)      { const int offs[6] = {0, 32768, 65536, 98304, 131072, 163840};
                      base = offs[m]; nc = n; }
    else if (m == 6){ base = 196608; nc = n; }
    else            { base = 196608; nc = 64 + n; }
    g_wb[base + nc * 128 + k]         = h;
    g_wb[base + 16384 + nc * 128 + k] = l;
}

// ================= CSR build (atomic allocation, no scan) =================
__global__ void czero_k() {
    int i = blockIdx.x * blockDim.x + threadIdx.x;
    if (i < NN) g_cnt[i] = 0;
    if (i == 0) g_total = 0;
}
__global__ void hist_k(const int* __restrict__ dst) {
    int e = blockIdx.x * blockDim.x + threadIdx.x;
    if (e < NE) atomicAdd(&g_cnt[dst[e]], 1);
}
__global__ void alloc_k() {
    int i = blockIdx.x * blockDim.x + threadIdx.x;
    if (i >= NN) return;
    int c = g_cnt[i];
    int beg = (c > 0) ? atomicAdd(&g_total, c) : 0;
    g_rowbeg[i] = beg;
    g_cur[i]    = beg;
}
__global__ void fill_k(const int* __restrict__ src, const int* __restrict__ dst) {
    int e = blockIdx.x * blockDim.x + threadIdx.x;
    if (e >= NE) return;
    int pos = atomicAdd(&g_cur[dst[e]], 1);
    g_eid[pos] = src[e];
}

// ================= gather aggregation: warp per node, pull model =================
// out[n] += (1/max(deg,1)) * sum_{s in N(n)} p[s]   (out pre-initialized with self term + bias)
__global__ __launch_bounds__(256)
void gath128_k(const float* __restrict__ p, float* __restrict__ out) {
    int w    = (blockIdx.x * 256 + threadIdx.x) >> 5;
    int lane = threadIdx.x & 31;
    if (w >= NN) return;
    int deg = g_cnt[w];
    int beg = g_rowbeg[w], end = beg + deg;
    float4 acc0 = make_float4(0.f, 0.f, 0.f, 0.f);
    float4 acc1 = make_float4(0.f, 0.f, 0.f, 0.f);
    int e = beg;
    for (; e + 3 < end; e += 4) {
        int s0 = g_eid[e], s1 = g_eid[e + 1], s2 = g_eid[e + 2], s3 = g_eid[e + 3];
        float4 v0 = *reinterpret_cast<const float4*>(p + (size_t)s0 * 128 + lane * 4);
        float4 v1 = *reinterpret_cast<const float4*>(p + (size_t)s1 * 128 + lane * 4);
        float4 v2 = *reinterpret_cast<const float4*>(p + (size_t)s2 * 128 + lane * 4);
        float4 v3 = *reinterpret_cast<const float4*>(p + (size_t)s3 * 128 + lane * 4);
        acc0.x += v0.x + v1.x; acc0.y += v0.y + v1.y;
        acc0.z += v0.z + v1.z; acc0.w += v0.w + v1.w;
        acc1.x += v2.x + v3.x; acc1.y += v2.y + v3.y;
        acc1.z += v2.z + v3.z; acc1.w += v2.w + v3.w;
    }
    for (; e < end; ++e) {
        int s0 = g_eid[e];
        float4 v0 = *reinterpret_cast<const float4*>(p + (size_t)s0 * 128 + lane * 4);
        acc0.x += v0.x; acc0.y += v0.y; acc0.z += v0.z; acc0.w += v0.w;
    }
    acc0.x += acc1.x; acc0.y += acc1.y; acc0.z += acc1.z; acc0.w += acc1.w;
    float inv = 1.0f / fmaxf((float)deg, 1.0f);
    float4 o = *reinterpret_cast<const float4*>(out + (size_t)w * 128 + lane * 4);
    o.x += acc0.x * inv; o.y += acc0.y * inv; o.z += acc0.z * inv; o.w += acc0.w * inv;
    *reinterpret_cast<float4*>(out + (size_t)w * 128 + lane * 4) = o;
}

__global__ __launch_bounds__(256)
void gath64_k(const float* __restrict__ p, float* __restrict__ out) {
    int w    = (blockIdx.x * 256 + threadIdx.x) >> 5;
    int lane = threadIdx.x & 31;
    if (w >= NN) return;
    int deg = g_cnt[w];
    int beg = g_rowbeg[w], end = beg + deg;
    float2 acc0 = make_float2(0.f, 0.f);
    float2 acc1 = make_float2(0.f, 0.f);
    int e = beg;
    for (; e + 3 < end; e += 4) {
        int s0 = g_eid[e], s1 = g_eid[e + 1], s2 = g_eid[e + 2], s3 = g_eid[e + 3];
        float2 v0 = *reinterpret_cast<const float2*>(p + (size_t)s0 * 64 + lane * 2);
        float2 v1 = *reinterpret_cast<const float2*>(p + (size_t)s1 * 64 + lane * 2);
        float2 v2 = *reinterpret_cast<const float2*>(p + (size_t)s2 * 64 + lane * 2);
        float2 v3 = *reinterpret_cast<const float2*>(p + (size_t)s3 * 64 + lane * 2);
        acc0.x += v0.x + v1.x; acc0.y += v0.y + v1.y;
        acc1.x += v2.x + v3.x; acc1.y += v2.y + v3.y;
    }
    for (; e < end; ++e) {
        int s0 = g_eid[e];
        float2 v0 = *reinterpret_cast<const float2*>(p + (size_t)s0 * 64 + lane * 2);
        acc0.x += v0.x; acc0.y += v0.y;
    }
    acc0.x += acc1.x; acc0.y += acc1.y;
    float inv = 1.0f / fmaxf((float)deg, 1.0f);
    float2 o = *reinterpret_cast<const float2*>(out + (size_t)w * 64 + lane * 2);
    o.x += acc0.x * inv; o.y += acc0.y * inv;
    *reinterpret_cast<float2*>(out + (size_t)w * 64 + lane * 2) = o;
}

// ================= GEMM building blocks =================
template<bool RELU>
__device__ __forceinline__ void loadA(char* dsm, const float* __restrict__ A, int m0, int M, int tid) {
    __nv_bfloat16* Ahi = reinterpret_cast<__nv_bfloat16*>(dsm);
    __nv_bfloat16* Alo = reinterpret_cast<__nv_bfloat16*>(dsm + ASZ);
#pragma unroll
    for (int i = 0; i < 8; ++i) {
        int idx = tid + i * 256;
        int m   = idx >> 5;
        int k0  = (idx & 31) * 4;
        float4 v = make_float4(0.f, 0.f, 0.f, 0.f);
        int gm = m0 + m;
        if (gm < M) v = *reinterpret_cast<const float4*>(A + (size_t)gm * 128 + k0);
        if (RELU) { v.x = fmaxf(v.x, 0.f); v.y = fmaxf(v.y, 0.f); v.z = fmaxf(v.z, 0.f); v.w = fmaxf(v.w, 0.f); }
        uint32_t h0, l0, h1, l1;
        split2(v.x, v.y, h0, l0);
        split2(v.z, v.w, h1, l1);
        *reinterpret_cast<uint2*>(&Ahi[m * PP + k0]) = make_uint2(h0, h1);
        *reinterpret_cast<uint2*>(&Alo[m * PP + k0]) = make_uint2(l0, l1);
    }
}

__device__ __forceinline__ void loadW(char* dsm, const __nv_bfloat16* __restrict__ whi,
                                      const __nv_bfloat16* __restrict__ wlo, int tid) {
    __nv_bfloat16* Whi = reinterpret_cast<__nv_bfloat16*>(dsm + WOFF);
    __nv_bfloat16* Wlo = reinterpret_cast<__nv_bfloat16*>(dsm + WOFF + ASZ * 2);
#pragma unroll
    for (int i = 0; i < 16; ++i) {
        int idx  = tid + i * 256;
        int half = idx >> 11;
        int r    = idx & 2047;
        int n    = r >> 4;
        int c    = r & 15;
        const uint4* srcp = reinterpret_cast<const uint4*>(half ? wlo : whi);
        __nv_bfloat16* dp = half ? Wlo : Whi;
        *reinterpret_cast<uint4*>(reinterpret_cast<char*>(&dp[n * PP]) + c * 16) = srcp[n * 16 + c];
    }
}

typedef wmma::fragment<wmma::accumulator, 16, 16, 16, float> AccF;

__device__ __forceinline__ void mmaStage(char* dsm, AccF acc[2][2], int wr, int wc) {
    __nv_bfloat16* Ahi = reinterpret_cast<__nv_bfloat16*>(dsm);
    __nv_bfloat16* Alo = reinterpret_cast<__nv_bfloat16*>(dsm + ASZ);
    __nv_bfloat16* Whi = reinterpret_cast<__nv_bfloat16*>(dsm + WOFF);
    __nv_bfloat16* Wlo = reinterpret_cast<__nv_bfloat16*>(dsm + WOFF + ASZ * 2);
#pragma unroll
    for (int i = 0; i < 2; ++i)
#pragma unroll
        for (int j = 0; j < 2; ++j) wmma::fill_fragment(acc[i][j], 0.0f);
#pragma unroll
    for (int ks = 0; ks < 8; ++ks) {
        const int k = ks * 16;
        wmma::fragment<wmma::matrix_a, 16, 16, 16, __nv_bfloat16, wmma::row_major> ah[2], al[2];
        wmma::fragment<wmma::matrix_b, 16, 16, 16, __nv_bfloat16, wmma::col_major> bh[2], bl[2];
#pragma unroll
        for (int i = 0; i < 2; ++i) {
            int m = wr * 32 + i * 16;
            wmma::load_matrix_sync(ah[i], &Ahi[m * PP + k], PP);
            wmma::load_matrix_sync(al[i], &Alo[m * PP + k], PP);
        }
#pragma unroll
        for (int j = 0; j < 2; ++j) {
            int n = wc * 32 + j * 16;
            wmma::load_matrix_sync(bh[j], &Whi[n * PP + k], PP);
            wmma::load_matrix_sync(bl[j], &Wlo[n * PP + k], PP);
        }
#pragma unroll
        for (int i = 0; i < 2; ++i)
#pragma unroll
            for (int j = 0; j < 2; ++j) {
                wmma::mma_sync(acc[i][j], ah[i], bh[j], acc[i][j]);
                wmma::mma_sync(acc[i][j], ah[i], bl[j], acc[i][j]);
                wmma::mma_sync(acc[i][j], al[i], bh[j], acc[i][j]);
            }
    }
}

__device__ __forceinline__ void accToStaging(char* dsm, AccF acc[2][2], int wr, int wc) {
    float* Cs = reinterpret_cast<float*>(dsm + WOFF);
#pragma unroll
    for (int i = 0; i < 2; ++i)
#pragma unroll
        for (int j = 0; j < 2; ++j)
            wmma::store_matrix_sync(&Cs[(wr * 32 + i * 16) * CP + wc * 32 + j * 16], acc[i][j], CP, wmma::mem_row_major);
}

__device__ __forceinline__ void stagingToA(char* dsm, const float* __restrict__ bias, int tid) {
    const float* Cs = reinterpret_cast<const float*>(dsm + WOFF);
    __nv_bfloat16* Ahi = reinterpret_cast<__nv_bfloat16*>(dsm);
    __nv_bfloat16* Alo = reinterpret_cast<__nv_bfloat16*>(dsm + ASZ);
#pragma unroll
    for (int i = 0; i < 8; ++i) {
        int idx = tid + i * 256;
        int m   = idx >> 5;
        int c   = (idx & 31) * 4;
        float4 v = *reinterpret_cast<const float4*>(&Cs[m * CP + c]);
        v.x = fmaxf(v.x + bias[c + 0], 0.f);
        v.y = fmaxf(v.y + bias[c + 1], 0.f);
        v.z = fmaxf(v.z + bias[c + 2], 0.f);
        v.w = fmaxf(v.w + bias[c + 3], 0.f);
        uint32_t h0, l0, h1, l1;
        split2(v.x, v.y, h0, l0);
        split2(v.z, v.w, h1, l1);
        *reinterpret_cast<uint2*>(&Ahi[m * PP + c]) = make_uint2(h0, h1);
        *reinterpret_cast<uint2*>(&Alo[m * PP + c]) = make_uint2(l0, l1);
    }
}

template<bool BIAS>
__device__ __forceinline__ void stagingToGlobal(char* dsm, const float* __restrict__ bias,
                                                float* __restrict__ C, int m0, int M, int tid) {
    const float* Cs = reinterpret_cast<const float*>(dsm + WOFF);
#pragma unroll
    for (int i = 0; i < 8; ++i) {
        int idx = tid + i * 256;
        int m   = idx >> 5;
        int c   = (idx & 31) * 4;
        int gm  = m0 + m;
        if (gm >= M) continue;
        float4 o = *reinterpret_cast<const float4*>(&Cs[m * CP + c]);
        if (BIAS) { o.x += bias[c]; o.y += bias[c + 1]; o.z += bias[c + 2]; o.w += bias[c + 3]; }
        *reinterpret_cast<float4*>(C + (size_t)gm * 128 + c) = o;
    }
}

// ================= fused kernels =================

// K1: x -> { self0(+b) -> p_a ; neigh0 -> p_p }
__global__ __launch_bounds__(256, 2)
void k1_k(const float* __restrict__ x,
          const __nv_bfloat16* __restrict__ s0h, const __nv_bfloat16* __restrict__ s0l,
          const __nv_bfloat16* __restrict__ n0h, const __nv_bfloat16* __restrict__ n0l,
          const float* __restrict__ b0, float* __restrict__ Ca, float* __restrict__ Cp, int M)
{
    extern __shared__ char dsm[];
    const int tid = threadIdx.x, wid = tid >> 5, wr = wid & 1, wc = wid >> 1;
    const int m0 = blockIdx.x * 64;
    AccF acc[2][2];

    loadA<false>(dsm, x, m0, M, tid);
    loadW(dsm, s0h, s0l, tid);
    __syncthreads();
    mmaStage(dsm, acc, wr, wc);
    __syncthreads();
    accToStaging(dsm, acc, wr, wc);
    __syncthreads();
    stagingToGlobal<true>(dsm, b0, Ca, m0, M, tid);
    __syncthreads();
    loadW(dsm, n0h, n0l, tid);
    __syncthreads();
    mmaStage(dsm, acc, wr, wc);
    __syncthreads();
    accToStaging(dsm, acc, wr, wc);
    __syncthreads();
    stagingToGlobal<false>(dsm, nullptr, Cp, m0, M, tid);
}

// K2: relu(conv0) -> fc(+b,relu) -> fc2(+b,relu) -> { self1(+b)->Cb ; neigh1->Cp }
__global__ __launch_bounds__(256, 2)
void k2_k(const float* __restrict__ Ain,
          const __nv_bfloat16* __restrict__ fch, const __nv_bfloat16* __restrict__ fcl, const float* __restrict__ fcb,
          const __nv_bfloat16* __restrict__ f2h, const __nv_bfloat16* __restrict__ f2l, const float* __restrict__ f2b,
          const __nv_bfloat16* __restrict__ s1h, const __nv_bfloat16* __restrict__ s1l, const float* __restrict__ b1,
          const __nv_bfloat16* __restrict__ n1h, const __nv_bfloat16* __restrict__ n1l,
          float* __restrict__ Cb, float* __restrict__ Cp, int M)
{
    extern __shared__ char dsm[];
    const int tid = threadIdx.x, wid = tid >> 5, wr = wid & 1, wc = wid >> 1;
    const int m0 = blockIdx.x * 64;
    AccF acc[2][2];

    loadA<true>(dsm, Ain, m0, M, tid);
    loadW(dsm, fch, fcl, tid);
    __syncthreads();
    mmaStage(dsm, acc, wr, wc);
    __syncthreads();
    accToStaging(dsm, acc, wr, wc);
    __syncthreads();
    stagingToA(dsm, fcb, tid);
    __syncthreads();
    loadW(dsm, f2h, f2l, tid);
    __syncthreads();
    mmaStage(dsm, acc, wr, wc);
    __syncthreads();
    accToStaging(dsm, acc, wr, wc);
    __syncthreads();
    stagingToA(dsm, f2b, tid);
    __syncthreads();
    loadW(dsm, s1h, s1l, tid);
    __syncthreads();
    mmaStage(dsm, acc, wr, wc);
    __syncthreads();
    accToStaging(dsm, acc, wr, wc);
    __syncthreads();
    stagingToGlobal<true>(dsm, b1, Cb, m0, M, tid);
    __syncthreads();
    loadW(dsm, n1h, n1l, tid);
    __syncthreads();
    mmaStage(dsm, acc, wr, wc);
    __syncthreads();
    accToStaging(dsm, acc, wr, wc);
    __syncthreads();
    stagingToGlobal<false>(dsm, nullptr, Cp, m0, M, tid);
}

// K3: relu(conv1) -> packed layer2 W: cols 0-63 -> out (+b2), 64-127 -> Cp (64-wide)
__global__ __launch_bounds__(256, 2)
void k3_k(const float* __restrict__ Ain,
          const __nv_bfloat16* __restrict__ l2h, const __nv_bfloat16* __restrict__ l2l,
          const float* __restrict__ b2, float* __restrict__ Co, float* __restrict__ Cp, int M)
{
    extern __shared__ char dsm[];
    const int tid = threadIdx.x, wid = tid >> 5, wr = wid & 1, wc = wid >> 1;
    const int m0 = blockIdx.x * 64;
    AccF acc[2][2];

    loadA<true>(dsm, Ain, m0, M, tid);
    loadW(dsm, l2h, l2l, tid);
    __syncthreads();
    mmaStage(dsm, acc, wr, wc);
    __syncthreads();
    accToStaging(dsm, acc, wr, wc);
    __syncthreads();
    const float* Cs = reinterpret_cast<const float*>(dsm + WOFF);
#pragma unroll
    for (int i = 0; i < 8; ++i) {
        int idx = tid + i * 256;
        int m   = idx >> 5;
        int c   = (idx & 31) * 4;
        int gm  = m0 + m;
        if (gm >= M) continue;
        float4 o = *reinterpret_cast<const float4*>(&Cs[m * CP + c]);
        if (c < 64) {
            o.x += b2[c]; o.y += b2[c + 1]; o.z += b2[c + 2]; o.w += b2[c + 3];
            *reinterpret_cast<float4*>(Co + (size_t)gm * 64 + c) = o;
        } else {
            *reinterpret_cast<float4*>(Cp + (size_t)gm * 64 + (c - 64)) = o;
        }
    }
}

// ---------------- launch ----------------
extern "C" void kernel_launch(void* const* d_in, const int* in_sizes, int n_in,
                              void* d_out, int out_size) {
    const float* x        = (const float*)d_in[0];
    const int*   src      = (const int*)  d_in[1];
    const int*   dst      = (const int*)  d_in[2];
    const float* w_self0  = (const float*)d_in[3];
    const float* b_self0  = (const float*)d_in[4];
    const float* w_neigh0 = (const float*)d_in[5];
    const float* fc_w     = (const float*)d_in[6];
    const float* fc_b     = (const float*)d_in[7];
    const float* fc2_w    = (const float*)d_in[8];
    const float* fc2_b    = (const float*)d_in[9];
    const float* w_self1  = (const float*)d_in[10];
    const float* b_self1  = (const float*)d_in[11];
    const float* w_neigh1 = (const float*)d_in[12];
    const float* w_self2  = (const float*)d_in[13];
    const float* b_self2  = (const float*)d_in[14];
    const float* w_neigh2 = (const float*)d_in[15];
    float* out = (float*)d_out;

    float *p_a, *p_b, *p_p;
    __nv_bfloat16* p_wb;
    cudaGetSymbolAddress((void**)&p_a,  g_a);
    cudaGetSymbolAddress((void**)&p_b,  g_b);
    cudaGetSymbolAddress((void**)&p_p,  g_p);
    cudaGetSymbolAddress((void**)&p_wb, g_wb);

    const __nv_bfloat16 *s0h = p_wb,          *s0l = p_wb + 16384;
    const __nv_bfloat16 *n0h = p_wb + 32768,  *n0l = p_wb + 49152;
    const __nv_bfloat16 *fch = p_wb + 65536,  *fcl = p_wb + 81920;
    const __nv_bfloat16 *f2h = p_wb + 98304,  *f2l = p_wb + 114688;
    const __nv_bfloat16 *s1h = p_wb + 131072, *s1l = p_wb + 147456;
    const __nv_bfloat16 *n1h = p_wb + 163840, *n1l = p_wb + 180224;
    const __nv_bfloat16 *l2h = p_wb + 196608, *l2l = p_wb + 212992;

    cudaFuncSetAttribute(k1_k, cudaFuncAttributeMaxDynamicSharedMemorySize, SMEMB);
    cudaFuncSetAttribute(k2_k, cudaFuncAttributeMaxDynamicSharedMemorySize, SMEMB);
    cudaFuncSetAttribute(k3_k, cudaFuncAttributeMaxDynamicSharedMemorySize, SMEMB);

    const int GB = (NN + 63) / 64;   // 1563
    const int T  = 256;
    const int GW = (NN * 32 + T - 1) / T;

    // ---- prep: CSR build (atomic alloc) + weight preconversion ----
    czero_k<<<(NN + T - 1) / T, T>>>();
    hist_k<<<(NE + T - 1) / T, T>>>(dst);
    alloc_k<<<(NN + T - 1) / T, T>>>();
    fill_k<<<(NE + T - 1) / T, T>>>(src, dst);
    WSrc ws; ws.s[0] = w_self0; ws.s[1] = w_neigh0; ws.s[2] = fc_w; ws.s[3] = fc2_w;
             ws.s[4] = w_self1; ws.s[5] = w_neigh1; ws.s[6] = w_self2; ws.s[7] = w_neigh2;
    wconv_k<<<(114688 + T - 1) / T, T>>>(ws);

    // ---- layer 0 ----
    k1_k<<<GB, T, SMEMB>>>(x, s0h, s0l, n0h, n0l, b_self0, p_a, p_p, NN);
    gath128_k<<<GW, T>>>(p_p, p_a);                                     // p_a = conv0 (pre-relu)

    // ---- fc / fc2 / layer 1 ----
    k2_k<<<GB, T, SMEMB>>>(p_a, fch, fcl, fc_b, f2h, f2l, fc2_b,
                           s1h, s1l, b_self1, n1h, n1l, p_b, p_p, NN);
    gath128_k<<<GW, T>>>(p_p, p_b);                                     // p_b = conv1 (pre-relu)

    // ---- layer 2 ----
    k3_k<<<GB, T, SMEMB>>>(p_b, l2h, l2l, b_self2, out, p_p, NN);
    gath64_k<<<GW, T>>>(p_p, out);
}